// round 7
// baseline (speedup 1.0000x reference)
#include <cuda_runtime.h>
#include <cuda_bf16.h>
#include <math.h>
#include <stdint.h>

// ---------------- problem constants ----------------
#define NN 512
#define BB 32
#define SEQ 8
#define NTAB 7001
#define SZT (BB * NN * NN)

static __device__ __constant__ float SQLF = 0.22360679775f;   // sqrt(0.05)

// ---------------- device scratch (no runtime alloc allowed) ----------------
__device__ float g_T[SZT];                     // T = M*rho fp32 (33.5 MB)
__device__ __nv_bfloat16 g_Ms[3][SZT];         // splits of M = W diag(s_b)
__device__ __nv_bfloat16 g_Rs[3][SZT];         // splits of rho
__device__ __nv_bfloat16 g_Ts[3][SZT];         // splits of T
__device__ float g_uA[BB * NN], g_sA[BB * NN];
__device__ float g_uB[BB * NN], g_sB[BB * NN];
__device__ float g_ulin[BB * NN], g_diag[BB * NN];
__device__ float g_chi[BB * NN], g_sout[BB * NN];
__device__ float g_ue[BB * NN], g_se[BB * NN];
__device__ float g_ueraw[BB * NN], g_se2[BB * NN];

// Dawson-style tables
__device__ double d_I[NTAB], d_g[NTAB], d_h[NTAB];
__device__ float GTt[NTAB], GIt[NTAB], HIt[NTAB], XGf[NTAB];

// ---------------- helpers ----------------
__device__ __forceinline__ uint32_t smem_u32(const void* p) {
    uint32_t a;
    asm("{ .reg .u64 t; cvta.to.shared.u64 t, %1; cvt.u32.u64 %0, t; }" : "=r"(a) : "l"(p));
    return a;
}
__device__ __forceinline__ void split3(float v, __nv_bfloat16& b1, __nv_bfloat16& b2, __nv_bfloat16& b3) {
    b1 = __float2bfloat16_rn(v);
    float r = v - __bfloat162float(b1);
    b2 = __float2bfloat16_rn(r);
    float r2 = r - __bfloat162float(b2);
    b3 = __float2bfloat16_rn(r2);
}
// D = A*B (C = 0): fresh partial, no long RZ chain inside the tensor core
__device__ __forceinline__ void mma16816_zc(float* d, const uint32_t* a, uint32_t b0, uint32_t b1) {
    asm volatile(
        "mma.sync.aligned.m16n8k16.row.col.f32.bf16.bf16.f32 "
        "{%0,%1,%2,%3}, {%4,%5,%6,%7}, {%8,%9}, {%10,%11,%12,%13};"
        : "=f"(d[0]), "=f"(d[1]), "=f"(d[2]), "=f"(d[3])
        : "r"(a[0]), "r"(a[1]), "r"(a[2]), "r"(a[3]), "r"(b0), "r"(b1),
          "f"(0.f), "f"(0.f), "f"(0.f), "f"(0.f));
}
// D += A*B (single chained step only)
__device__ __forceinline__ void mma16816(float* c, const uint32_t* a, uint32_t b0, uint32_t b1) {
    asm volatile(
        "mma.sync.aligned.m16n8k16.row.col.f32.bf16.bf16.f32 "
        "{%0,%1,%2,%3}, {%4,%5,%6,%7}, {%8,%9}, {%0,%1,%2,%3};"
        : "+f"(c[0]), "+f"(c[1]), "+f"(c[2]), "+f"(c[3])
        : "r"(a[0]), "r"(a[1]), "r"(a[2]), "r"(a[3]), "r"(b0), "r"(b1));
}
#define CP_ASYNC16(dst, src) \
    asm volatile("cp.async.cg.shared.global [%0], [%1], 16;" :: "r"(dst), "l"(src))
#define CP_COMMIT() asm volatile("cp.async.commit_group;" ::: "memory")
#define CP_WAIT1()  asm volatile("cp.async.wait_group 1;" ::: "memory")
#define CP_WAIT0()  asm volatile("cp.async.wait_group 0;" ::: "memory")

// ---------------- table construction (fp64, matches numpy cumtrapz) ----------------
__device__ __forceinline__ double block_excl_scan(double local, double* part, int t) {
    part[t] = local;
    __syncthreads();
    for (int off = 1; off < 1024; off <<= 1) {
        double v = (t >= off) ? part[t - off] : 0.0;
        __syncthreads();
        part[t] += v;
        __syncthreads();
    }
    double incl = part[t];
    __syncthreads();
    return incl - local;
}

__global__ void build_tables_kernel() {
    const double DX = 14.0 / 7000.0;
    __shared__ double part[1024];
    int t = threadIdx.x;
    int start = t * 7;
    int end = start + 7;
    if (start > NTAB) start = NTAB;
    if (end > NTAB) end = NTAB;

    {
        double local = 0.0;
        for (int i = start; i < end; i++) {
            if (i > 0) {
                double x0 = -10.0 + (i - 1) * DX, x1 = -10.0 + i * DX;
                local += 0.5 * (exp(-x0 * x0) + exp(-x1 * x1)) * DX;
            }
        }
        double run = block_excl_scan(local, part, t);
        const double A0 = exp(-100.0) / 20.0;
        for (int i = start; i < end; i++) {
            if (i > 0) {
                double x0 = -10.0 + (i - 1) * DX, x1 = -10.0 + i * DX;
                run += 0.5 * (exp(-x0 * x0) + exp(-x1 * x1)) * DX;
            }
            d_I[i] = A0 + run;
            XGf[i] = (float)(-10.0 + i * DX);
        }
    }
    __syncthreads();
    for (int i = start; i < end; i++) {
        double x = -10.0 + i * DX;
        double g = exp(x * x) * d_I[i];
        d_g[i] = g;
        GTt[i] = (float)g;
    }
    __syncthreads();
    {
        double local = 0.0;
        for (int i = start; i < end; i++)
            if (i > 0) local += 0.5 * (d_g[i - 1] + d_g[i]) * DX;
        double run = block_excl_scan(local, part, t);
        for (int i = start; i < end; i++) {
            if (i > 0) run += 0.5 * (d_g[i - 1] + d_g[i]) * DX;
            GIt[i] = (float)run;
        }
    }
    __syncthreads();
    {
        double local = 0.0;
        for (int i = start; i < end; i++) {
            if (i > 0) {
                double xa = -10.0 + (i - 1) * DX, xb = -10.0 + i * DX;
                double fa = exp(-xa * xa) * d_g[i - 1] * d_g[i - 1];
                double fb = exp(-xb * xb) * d_g[i] * d_g[i];
                local += 0.5 * (fa + fb) * DX;
            }
        }
        double run = block_excl_scan(local, part, t);
        for (int i = start; i < end; i++) {
            if (i > 0) {
                double xa = -10.0 + (i - 1) * DX, xb = -10.0 + i * DX;
                double fa = exp(-xa * xa) * d_g[i - 1] * d_g[i - 1];
                double fb = exp(-xb * xb) * d_g[i] * d_g[i];
                run += 0.5 * (fa + fb) * DX;
            }
            double x = -10.0 + i * DX;
            d_h[i] = exp(x * x) * run;
        }
    }
    __syncthreads();
    {
        double local = 0.0;
        for (int i = start; i < end; i++)
            if (i > 0) local += 0.5 * (d_h[i - 1] + d_h[i]) * DX;
        double run = block_excl_scan(local, part, t);
        for (int i = start; i < end; i++) {
            if (i > 0) run += 0.5 * (d_h[i - 1] + d_h[i]) * DX;
            HIt[i] = (float)run;
        }
    }
}

// ---------------- small helper kernels ----------------
__global__ void init_copy_kernel(const float* __restrict__ u_in, const float* __restrict__ s_in) {
    int i = blockIdx.x * blockDim.x + threadIdx.x;
    if (i < BB * NN) { g_uA[i] = u_in[i]; g_sA[i] = s_in[i]; }
}

__global__ void ext_gemm_kernel(const float* __restrict__ We, const float* __restrict__ ue_in,
                                const float* __restrict__ se_in, const float* __restrict__ be) {
    int warp = threadIdx.x >> 5, lane = threadIdx.x & 31;
    int i = blockIdx.x * 8 + warp;
    int b = blockIdx.y;
    const float* wr = We + (size_t)i * NN;
    const float* ur = ue_in + (size_t)b * NN;
    const float* sr = se_in + (size_t)b * NN;
    float s1 = 0.f, s2 = 0.f;
    for (int k = lane; k < NN; k += 32) {
        float w = wr[k], sv = sr[k];
        s1 += w * ur[k];
        s2 += w * w * sv * sv;
    }
#pragma unroll
    for (int o = 16; o; o >>= 1) {
        s1 += __shfl_xor_sync(0xffffffffu, s1, o);
        s2 += __shfl_xor_sync(0xffffffffu, s2, o);
    }
    if (lane == 0) {
        g_ueraw[b * NN + i] = s1 + be[i];
        g_se2[b * NN + i] = s2;
    }
}

__global__ void ext_bn_kernel(const float* __restrict__ wme, const float* __restrict__ bme) {
    int i = threadIdx.x;
    float m = 0.f;
    for (int b = 0; b < BB; b++) m += g_ueraw[b * NN + i];
    m *= (1.0f / BB);
    float v = 0.f;
    for (int b = 0; b < BB; b++) { float d = g_ueraw[b * NN + i] - m; v += d * d; }
    v *= (1.0f / BB);
    float f = wme[i] / sqrtf(v + 1e-5f);
    float af = fabsf(f);
    float bmv = bme[i];
    for (int b = 0; b < BB; b++) {
        int idx = b * NN + i;
        g_se[idx] = sqrtf(g_se2[idx]) * af;
        g_ue[idx] = (g_ueraw[idx] - m) * f + bmv;
    }
}

__global__ void diag_ulin_kernel(const float* __restrict__ W, const float* __restrict__ bias,
                                 const float* __restrict__ u_cur, const float* __restrict__ s_cur) {
    int warp = threadIdx.x >> 5, lane = threadIdx.x & 31;
    int i = blockIdx.x * 8 + warp;
    int b = blockIdx.y;
    const float* wr = W + (size_t)i * NN;
    const float* tr = g_T + ((size_t)b * NN + i) * NN;
    const float* ur = u_cur + (size_t)b * NN;
    const float* sr = s_cur + (size_t)b * NN;
    float s1 = 0.f, s2 = 0.f;
    for (int k = lane; k < NN; k += 32) {
        float w = wr[k];
        s1 += w * ur[k];
        s2 += tr[k] * w * sr[k];
    }
#pragma unroll
    for (int o = 16; o; o >>= 1) {
        s1 += __shfl_xor_sync(0xffffffffu, s1, o);
        s2 += __shfl_xor_sync(0xffffffffu, s2, o);
    }
    if (lane == 0) {
        g_ulin[b * NN + i] = s1 + bias[i];
        g_diag[b * NN + i] = s2;
    }
}

__device__ __forceinline__ void interp_idx(float x, int& iq, float& fr) {
    float t = (x + 10.0f) * 500.0f;
    int i = (int)t;
    i = max(0, min(i, NTAB - 2));
    float x0 = __ldg(&XGf[i]);
    float x1 = __ldg(&XGf[i + 1]);
    if (x < x0 && i > 0) { i--; x1 = x0; x0 = __ldg(&XGf[i]); }
    else if (x >= x1 && i < NTAB - 2) { i++; x0 = x1; x1 = __ldg(&XGf[i + 1]); }
    iq = i;
    fr = (x - x0) / (x1 - x0);
}
__device__ __forceinline__ float interp_at(int i, float fr, const float* __restrict__ tab) {
    float lo = __ldg(&tab[i]);
    float hi = __ldg(&tab[i + 1]);
    return lo + fr * (hi - lo);
}

__global__ void bn_act_kernel(const float* __restrict__ wm, const float* __restrict__ bm,
                              float* __restrict__ u_nxt, float* __restrict__ s_nxt,
                              float* __restrict__ ou, float* __restrict__ os) {
    int i = threadIdx.x;
    float m = 0.f;
    for (int b = 0; b < BB; b++) m += g_ulin[b * NN + i];
    m *= (1.0f / BB);
    float v = 0.f;
    for (int b = 0; b < BB; b++) { float d = g_ulin[b * NN + i] - m; v += d * d; }
    v *= (1.0f / BB);
    float f = wm[i] / sqrtf(v + 1e-5f);
    float af = fabsf(f);
    float bmv = bm[i];
#pragma unroll 4
    for (int b = 0; b < BB; b++) {
        int idx = b * NN + i;
        float so = sqrtf(fmaxf(g_diag[idx], 0.f));
        float sbn = so * af;
        float se = g_se[idx];
        float st = sqrtf(sbn * sbn + se * se);
        float ut = (g_ulin[idx] - m) * f + bmv + g_ue[idx];
        float ss = fmaxf(st, 1e-6f);
        float inv = 1.0f / (ss * SQLF);
        float ub = fminf(fmaxf((1.0f - ut) * inv, -10.f), 4.f);
        float lb = fminf(fmaxf((-ut) * inv, -10.f), 4.f);
        int iu, il; float fu, fl;
        interp_idx(ub, iu, fu);
        interp_idx(lb, il, fl);
        float dG = interp_at(iu, fu, GIt) - interp_at(il, fl, GIt);
        float ua = 1.0f / (5.0f + 40.0f * dG);
        float dH = fmaxf(interp_at(iu, fu, HIt) - interp_at(il, fl, HIt), 0.f);
        float sa = sqrtf(3200.0f * dH * ua * ua * ua);
        float dg = interp_at(iu, fu, GTt) - interp_at(il, fl, GTt);
        float chi = ua * ua * 40.0f * dg / (SQLF * fmaxf(sa, 1e-9f));
        u_nxt[idx] = ua;
        s_nxt[idx] = sa;
        g_chi[idx] = chi;
        g_sout[idx] = so;
        if (ou) { ou[idx] = ua; os[idx] = sa; }
    }
}

// ---------------- split kernels ----------------
__global__ void msplit_kernel(const float* __restrict__ W, const float* __restrict__ s_cur) {
    int q = blockIdx.x * blockDim.x + threadIdx.x;
    int base = q * 4;
    int k = base & (NN - 1);
    int i = (base >> 9) & (NN - 1);
    int b = base >> 18;
    float4 w = *reinterpret_cast<const float4*>(&W[(size_t)i * NN + k]);
    float4 sv = *reinterpret_cast<const float4*>(&s_cur[(size_t)b * NN + k]);
    float m[4] = {w.x * sv.x, w.y * sv.y, w.z * sv.z, w.w * sv.w};
    union { __nv_bfloat16 h[4]; uint2 u; } p1, p2, p3;
#pragma unroll
    for (int j = 0; j < 4; j++) split3(m[j], p1.h[j], p2.h[j], p3.h[j]);
    *reinterpret_cast<uint2*>(&g_Ms[0][base]) = p1.u;
    *reinterpret_cast<uint2*>(&g_Ms[1][base]) = p2.u;
    *reinterpret_cast<uint2*>(&g_Ms[2][base]) = p3.u;
}

__global__ void rsplit_kernel(const float* __restrict__ rho_in) {
    int q = blockIdx.x * blockDim.x + threadIdx.x;
    int base = q * 4;
    float4 v = *reinterpret_cast<const float4*>(&rho_in[base]);
    float m[4] = {v.x, v.y, v.z, v.w};
    union { __nv_bfloat16 h[4]; uint2 u; } p1, p2, p3;
#pragma unroll
    for (int j = 0; j < 4; j++) split3(m[j], p1.h[j], p2.h[j], p3.h[j]);
    *reinterpret_cast<uint2*>(&g_Rs[0][base]) = p1.u;
    *reinterpret_cast<uint2*>(&g_Rs[1][base]) = p2.u;
    *reinterpret_cast<uint2*>(&g_Rs[2][base]) = p3.u;
}

// ---------------- HMMA batched GEMM (bf16 3-split, 8 products, RN outer accumulation) ----------------
// Per (product, 32k-chunk): fresh C=0 partial (2 chained HMMAs max), then fp32 RN add into racc.
// This bounds the tensor core's internal RZ-truncation bias (Ootomo-style).
#define KC 32
#define RPAD 40
#define TILEB (128 * RPAD * 2)          // 10240 B
#define STAGEB (6 * TILEB)              // 61440 B
#define SMEM_MMA (2 * STAGEB)           // 122880 B

__global__ void __launch_bounds__(256, 1)
mma_gemm_kernel(int mode, float* __restrict__ fdst) {
    extern __shared__ char sm[];
    const uint32_t sb = smem_u32(sm);
    const int tid = threadIdx.x;
    const int wid = tid >> 5;
    const int lane = tid & 31;
    const int g = lane >> 2;            // 0..7
    const int tig = lane & 3;           // 0..3
    const int wr = wid & 3;             // warp row (32 rows each)
    const int wc = wid >> 2;            // warp col (64 cols each)
    const int b = blockIdx.z;
    const int rowBase = blockIdx.y * 128;
    const int colBase = blockIdx.x * 128;

    const __nv_bfloat16* src[6];
    if (mode == 0) {
        src[0] = g_Ms[0]; src[1] = g_Ms[1]; src[2] = g_Ms[2];
        src[3] = g_Rs[0]; src[4] = g_Rs[1]; src[5] = g_Rs[2];
    } else {
        src[0] = g_Ts[0]; src[1] = g_Ts[1]; src[2] = g_Ts[2];
        src[3] = g_Ms[0]; src[4] = g_Ms[1]; src[5] = g_Ms[2];
    }
    const size_t aoff = ((size_t)(b * NN + rowBase)) * NN;
    const size_t boff = ((size_t)(b * NN + colBase)) * NN;

    auto issue_chunk = [&](int c, int st) {
        uint32_t dstBase = sb + st * STAGEB;
#pragma unroll
        for (int i = 0; i < 12; i++) {
            int idx = tid + i * 256;
            int tile = idx >> 9;
            int rem = idx & 511;
            int r = rem >> 2, c16 = rem & 3;
            size_t go = (tile < 3 ? aoff : boff) + (size_t)r * NN + c * KC + c16 * 8;
            const void* s = (const void*)(src[tile] + go);
            uint32_t d = dstBase + tile * TILEB + r * (RPAD * 2) + c16 * 16;
            CP_ASYNC16(d, s);
        }
    };

    float racc[2][8][4];
#pragma unroll
    for (int i = 0; i < 2; i++)
#pragma unroll
        for (int j = 0; j < 8; j++)
#pragma unroll
            for (int q = 0; q < 4; q++) racc[i][j][q] = 0.f;

    issue_chunk(0, 0);
    CP_COMMIT();

    const int P8[8] = {0, 1, 0, 2, 1, 0, 2, 1};
    const int Q8[8] = {0, 0, 1, 0, 1, 2, 1, 2};

    for (int c = 0; c < 16; c++) {
        int st = c & 1;
        if (c + 1 < 16) {
            issue_chunk(c + 1, (c + 1) & 1);
            CP_COMMIT();
            CP_WAIT1();
        } else {
            CP_WAIT0();
        }
        __syncthreads();

        const char* stage = sm + st * STAGEB;
        // A fragments: all 3 splits, both k-steps
        uint32_t af[3][2][2][4];
#pragma unroll
        for (int p = 0; p < 3; p++) {
            const char* pA = stage + p * TILEB;
#pragma unroll
            for (int ks = 0; ks < 2; ks++) {
                int k0 = ks * 16;
#pragma unroll
                for (int ms = 0; ms < 2; ms++) {
                    int r0 = wr * 32 + ms * 16;
                    af[p][ks][ms][0] = *reinterpret_cast<const uint32_t*>(pA + (r0 + g) * (RPAD * 2) + (k0 + tig * 2) * 2);
                    af[p][ks][ms][1] = *reinterpret_cast<const uint32_t*>(pA + (r0 + g + 8) * (RPAD * 2) + (k0 + tig * 2) * 2);
                    af[p][ks][ms][2] = *reinterpret_cast<const uint32_t*>(pA + (r0 + g) * (RPAD * 2) + (k0 + tig * 2 + 8) * 2);
                    af[p][ks][ms][3] = *reinterpret_cast<const uint32_t*>(pA + (r0 + g + 8) * (RPAD * 2) + (k0 + tig * 2 + 8) * 2);
                }
            }
        }
#pragma unroll
        for (int nh = 0; nh < 2; nh++) {
            // B fragments: 3 splits, both k-steps, 4 n-tiles
            uint32_t bfr[3][2][4][2];
#pragma unroll
            for (int q = 0; q < 3; q++) {
                const char* pB = stage + (3 + q) * TILEB;
#pragma unroll
                for (int ks = 0; ks < 2; ks++) {
                    int k0 = ks * 16;
#pragma unroll
                    for (int n4 = 0; n4 < 4; n4++) {
                        int n0 = wc * 64 + nh * 32 + n4 * 8;
                        bfr[q][ks][n4][0] = *reinterpret_cast<const uint32_t*>(pB + (n0 + g) * (RPAD * 2) + (k0 + tig * 2) * 2);
                        bfr[q][ks][n4][1] = *reinterpret_cast<const uint32_t*>(pB + (n0 + g) * (RPAD * 2) + (k0 + tig * 2 + 8) * 2);
                    }
                }
            }
#pragma unroll
            for (int pr = 0; pr < 8; pr++) {
                int p = P8[pr], q = Q8[pr];
#pragma unroll
                for (int ms = 0; ms < 2; ms++) {
#pragma unroll
                    for (int n4 = 0; n4 < 4; n4++) {
                        float ta[4];
                        mma16816_zc(ta, af[p][0][ms], bfr[q][0][n4][0], bfr[q][0][n4][1]);
                        mma16816(ta, af[p][1][ms], bfr[q][1][n4][0], bfr[q][1][n4][1]);
                        int nn = nh * 4 + n4;
                        racc[ms][nn][0] += ta[0];
                        racc[ms][nn][1] += ta[1];
                        racc[ms][nn][2] += ta[2];
                        racc[ms][nn][3] += ta[3];
                    }
                }
            }
        }
        __syncthreads();
    }

    // ---- epilogue ----
    if (mode == 0) {
#pragma unroll
        for (int ms = 0; ms < 2; ms++) {
#pragma unroll
            for (int half = 0; half < 2; half++) {
                int gi = rowBase + wr * 32 + ms * 16 + g + half * 8;
                size_t rowo = ((size_t)(b * NN + gi)) * NN;
#pragma unroll
                for (int ns = 0; ns < 8; ns++) {
                    int l0 = colBase + wc * 64 + ns * 8 + tig * 2;
                    float c0 = racc[ms][ns][half * 2 + 0];
                    float c1 = racc[ms][ns][half * 2 + 1];
                    *reinterpret_cast<float2*>(&g_T[rowo + l0]) = make_float2(c0, c1);
                    __nv_bfloat16 x1, x2, x3, y1, y2, y3;
                    split3(c0, x1, x2, x3);
                    split3(c1, y1, y2, y3);
                    union { __nv_bfloat16 h[2]; uint32_t u; } u1, u2, u3;
                    u1.h[0] = x1; u1.h[1] = y1;
                    u2.h[0] = x2; u2.h[1] = y2;
                    u3.h[0] = x3; u3.h[1] = y3;
                    *reinterpret_cast<uint32_t*>(&g_Ts[0][rowo + l0]) = u1.u;
                    *reinterpret_cast<uint32_t*>(&g_Ts[1][rowo + l0]) = u2.u;
                    *reinterpret_cast<uint32_t*>(&g_Ts[2][rowo + l0]) = u3.u;
                }
            }
        }
    } else {
#pragma unroll
        for (int ms = 0; ms < 2; ms++) {
#pragma unroll
            for (int half = 0; half < 2; half++) {
                int gi = rowBase + wr * 32 + ms * 16 + g + half * 8;
                size_t rowo = ((size_t)(b * NN + gi)) * NN;
                float chI = __ldg(&g_chi[b * NN + gi]);
                float soI = __ldg(&g_sout[b * NN + gi]);
#pragma unroll
                for (int ns = 0; ns < 8; ns++) {
                    int l0 = colBase + wc * 64 + ns * 8 + tig * 2;
                    float rv[2];
#pragma unroll
                    for (int q = 0; q < 2; q++) {
                        int l = l0 + q;
                        float cv = racc[ms][ns][half * 2 + q];
                        float chL = __ldg(&g_chi[b * NN + l]);
                        float soL = __ldg(&g_sout[b * NN + l]);
                        float denom = soI * soL;
                        float qq = (denom > 1e-12f) ? cv / denom : 0.0f;
                        rv[q] = (gi == l) ? 1.0f : chI * chL * qq;
                    }
                    __nv_bfloat16 x1, x2, x3, y1, y2, y3;
                    split3(rv[0], x1, x2, x3);
                    split3(rv[1], y1, y2, y3);
                    union { __nv_bfloat16 h[2]; uint32_t u; } u1, u2, u3;
                    u1.h[0] = x1; u1.h[1] = y1;
                    u2.h[0] = x2; u2.h[1] = y2;
                    u3.h[0] = x3; u3.h[1] = y3;
                    *reinterpret_cast<uint32_t*>(&g_Rs[0][rowo + l0]) = u1.u;
                    *reinterpret_cast<uint32_t*>(&g_Rs[1][rowo + l0]) = u2.u;
                    *reinterpret_cast<uint32_t*>(&g_Rs[2][rowo + l0]) = u3.u;
                    if (fdst)
                        *reinterpret_cast<float2*>(&fdst[rowo + l0]) = make_float2(rv[0], rv[1]);
                }
            }
        }
    }
}

// ---------------- launch ----------------
extern "C" void kernel_launch(void* const* d_in, const int* in_sizes, int n_in,
                              void* d_out, int out_size) {
    const float* u_in     = (const float*)d_in[0];
    const float* s_in     = (const float*)d_in[1];
    const float* rho_in   = (const float*)d_in[2];
    const float* uext     = (const float*)d_in[3];
    const float* sext     = (const float*)d_in[4];
    const float* W        = (const float*)d_in[5];
    const float* bias     = (const float*)d_in[6];
    const float* Wext     = (const float*)d_in[7];
    const float* bext     = (const float*)d_in[8];
    const float* wmean    = (const float*)d_in[9];
    const float* bmean    = (const float*)d_in[10];
    const float* wmeanext = (const float*)d_in[11];
    const float* bmeanext = (const float*)d_in[12];
    (void)in_sizes; (void)n_in; (void)out_size;

    float* out = (float*)d_out;
    float* out_u = out;
    float* out_s = out + BB * NN;
    float* out_rho = out + 2 * BB * NN;

    cudaFuncSetAttribute(mma_gemm_kernel, cudaFuncAttributeMaxDynamicSharedMemorySize, SMEM_MMA);

    build_tables_kernel<<<1, 1024>>>();
    init_copy_kernel<<<32, 512>>>(u_in, s_in);
    ext_gemm_kernel<<<dim3(64, 32), 256>>>(Wext, uext, sext, bext);
    ext_bn_kernel<<<1, 512>>>(wmeanext, bmeanext);
    rsplit_kernel<<<SZT / 4 / 256, 256>>>(rho_in);

    float *uA, *sA, *uB, *sB;
    cudaGetSymbolAddress((void**)&uA, g_uA);
    cudaGetSymbolAddress((void**)&sA, g_sA);
    cudaGetSymbolAddress((void**)&uB, g_uB);
    cudaGetSymbolAddress((void**)&sB, g_sB);

    dim3 gg(4, 4, BB);
    float* u_cur = uA; float* s_cur = sA;
    float* u_nxt = uB; float* s_nxt = sB;
    for (int t = 0; t < SEQ; t++) {
        bool last = (t == SEQ - 1);
        msplit_kernel<<<SZT / 4 / 256, 256>>>(W, s_cur);
        mma_gemm_kernel<<<gg, 256, SMEM_MMA>>>(0, (float*)nullptr);
        diag_ulin_kernel<<<dim3(64, 32), 256>>>(W, bias, u_cur, s_cur);
        bn_act_kernel<<<1, 512>>>(wmean, bmean, u_nxt, s_nxt,
                                  last ? out_u : (float*)nullptr,
                                  last ? out_s : (float*)nullptr);
        mma_gemm_kernel<<<gg, 256, SMEM_MMA>>>(1, last ? out_rho : (float*)nullptr);
        float* tu = u_cur; u_cur = u_nxt; u_nxt = tu;
        float* ts = s_cur; s_cur = s_nxt; s_nxt = ts;
    }
}